// round 1
// baseline (speedup 1.0000x reference)
#include <cuda_runtime.h>
#include <math.h>

// Problem constants
constexpr int B_  = 4;
constexpr int S_  = 2048;
constexpr int D_  = 1024;
constexpr int H_  = 16;
constexpr int DK_ = 64;
constexpr int BH_ = B_ * H_;   // 64

// Scratch buffers (allocation-free; module-scope device globals)
// layout q/k/v: [B,H,S,DK]  -> index ((bh)*S + s)*DK + k
// layout att:   [B,S,D]     -> index (b*S + s)*D + h*DK + k   (already "concat heads")
__device__ float g_q[8388608];
__device__ float g_k[8388608];
__device__ float g_v[8388608];
__device__ float g_att[8388608];

// ---------------------------------------------------------------------------
// QKV projection: for each (s-tile, b, h, {q,k,v}):
//   C[64x64] = X[b, s0:s0+64, :1024] @ W[h][1024x64]
// ---------------------------------------------------------------------------
__global__ __launch_bounds__(256) void qkv_kernel(
    const float* __restrict__ x,
    const float* __restrict__ Wq,
    const float* __restrict__ Wk,
    const float* __restrict__ Wv)
{
    __shared__ float As[16][65];   // As[k][m]  (transposed X tile)
    __shared__ float Bs[16][65];   // Bs[k][n]

    const int stile = blockIdx.x;
    const int bh    = blockIdx.y;
    const int b     = bh >> 4;
    const int h     = bh & 15;

    const float* W    = (blockIdx.z == 0) ? Wq : (blockIdx.z == 1) ? Wk : Wv;
    float*       outp = (blockIdx.z == 0) ? g_q : (blockIdx.z == 1) ? g_k : g_v;

    const float* Ab = x + ((long)b * S_ + (long)stile * 64) * D_;  // row stride D_
    const float* Bb = W + (long)h * D_ * DK_;                      // row stride DK_

    const int tid = threadIdx.x;
    const int tx  = tid & 15;
    const int ty  = tid >> 4;
    const int ak  = tid & 15, am = tid >> 4;   // A loader: k, m
    const int bn  = tid & 63, bk = tid >> 6;   // B loader: n, k

    float acc[4][4] = {};

    for (int k0 = 0; k0 < D_; k0 += 16) {
        #pragma unroll
        for (int i = 0; i < 4; i++)
            As[ak][am + 16 * i] = Ab[(am + 16 * i) * D_ + k0 + ak];
        #pragma unroll
        for (int i = 0; i < 4; i++)
            Bs[bk + 4 * i][bn] = Bb[(k0 + bk + 4 * i) * DK_ + bn];
        __syncthreads();

        #pragma unroll
        for (int kk = 0; kk < 16; kk++) {
            float a[4], bb[4];
            #pragma unroll
            for (int i = 0; i < 4; i++) a[i]  = As[kk][ty * 4 + i];
            #pragma unroll
            for (int j = 0; j < 4; j++) bb[j] = Bs[kk][tx * 4 + j];
            #pragma unroll
            for (int i = 0; i < 4; i++)
                #pragma unroll
                for (int j = 0; j < 4; j++)
                    acc[i][j] += a[i] * bb[j];
        }
        __syncthreads();
    }

    float* ob = outp + ((long)bh * S_ + (long)stile * 64) * DK_;
    #pragma unroll
    for (int i = 0; i < 4; i++)
        #pragma unroll
        for (int j = 0; j < 4; j++)
            ob[(ty * 4 + i) * DK_ + tx * 4 + j] = acc[i][j];
}

// ---------------------------------------------------------------------------
// Flash attention, causal, per (q-tile of 64, b*h). Online softmax.
// dyn smem: Qs[64][64] | Ks[64][65] | Vs[64][65] | Ps[64][64]
// ---------------------------------------------------------------------------
__global__ __launch_bounds__(256) void attn_kernel()
{
    extern __shared__ float sm[];
    float* Qs = sm;                 // 64*64
    float* Ks = Qs + 64 * 64;       // 64*65
    float* Vs = Ks + 64 * 65;       // 64*65
    float* Ps = Vs + 64 * 65;       // 64*64

    const int q0  = blockIdx.x * 64;
    const int bh  = blockIdx.y;
    const int tid = threadIdx.x;
    const int tx  = tid & 15;
    const int ty  = tid >> 4;

    const float* qg = g_q + ((long)bh * S_ + q0) * DK_;
    for (int idx = tid; idx < 64 * 64; idx += 256)
        Qs[idx] = qg[idx];

    float m_i[4], l_i[4], o[4][4];
    #pragma unroll
    for (int i = 0; i < 4; i++) {
        m_i[i] = -1e30f;
        l_i[i] = 0.0f;
        #pragma unroll
        for (int j = 0; j < 4; j++) o[i][j] = 0.0f;
    }
    const float scale = 0.125f;  // 1/sqrt(64)

    for (int kv0 = 0; kv0 <= q0; kv0 += 64) {
        const float* kg = g_k + ((long)bh * S_ + kv0) * DK_;
        const float* vg = g_v + ((long)bh * S_ + kv0) * DK_;
        for (int idx = tid; idx < 64 * 64; idx += 256) {
            int r = idx >> 6, c = idx & 63;
            Ks[r * 65 + c] = kg[idx];
            Vs[r * 65 + c] = vg[idx];
        }
        __syncthreads();

        // S = Q @ K^T  (64x64, K-inner over dk)
        float sacc[4][4] = {};
        #pragma unroll
        for (int k = 0; k < 64; k++) {
            float a[4], bb[4];
            #pragma unroll
            for (int i = 0; i < 4; i++) a[i]  = Qs[(ty * 4 + i) * 64 + k];
            #pragma unroll
            for (int j = 0; j < 4; j++) bb[j] = Ks[(tx * 4 + j) * 65 + k];
            #pragma unroll
            for (int i = 0; i < 4; i++)
                #pragma unroll
                for (int j = 0; j < 4; j++)
                    sacc[i][j] += a[i] * bb[j];
        }

        const bool diag = (kv0 == q0);

        #pragma unroll
        for (int i = 0; i < 4; i++) {
            const int qpos = q0 + ty * 4 + i;
            float s4[4];
            #pragma unroll
            for (int j = 0; j < 4; j++) {
                float s = sacc[i][j] * scale;
                if (diag && (kv0 + tx * 4 + j) > qpos) s = -1e30f;
                s4[j] = s;
            }
            // row max across 4 local + 16 tx lanes (tx = lane bits [0:4))
            float mt = fmaxf(fmaxf(s4[0], s4[1]), fmaxf(s4[2], s4[3]));
            #pragma unroll
            for (int off = 1; off < 16; off <<= 1)
                mt = fmaxf(mt, __shfl_xor_sync(0xffffffffu, mt, off));
            float mnew = fmaxf(m_i[i], mt);
            float p[4], ls = 0.0f;
            #pragma unroll
            for (int j = 0; j < 4; j++) { p[j] = __expf(s4[j] - mnew); ls += p[j]; }
            #pragma unroll
            for (int off = 1; off < 16; off <<= 1)
                ls += __shfl_xor_sync(0xffffffffu, ls, off);
            float alpha = __expf(m_i[i] - mnew);
            l_i[i] = l_i[i] * alpha + ls;
            m_i[i] = mnew;
            #pragma unroll
            for (int j = 0; j < 4; j++)
                Ps[(ty * 4 + i) * 64 + tx * 4 + j] = p[j];
            #pragma unroll
            for (int j = 0; j < 4; j++) o[i][j] *= alpha;
        }
        __syncthreads();

        // O += P @ V (inner over kv)
        #pragma unroll
        for (int c = 0; c < 64; c++) {
            float a[4], bb[4];
            #pragma unroll
            for (int i = 0; i < 4; i++) a[i]  = Ps[(ty * 4 + i) * 64 + c];
            #pragma unroll
            for (int j = 0; j < 4; j++) bb[j] = Vs[c * 65 + tx * 4 + j];
            #pragma unroll
            for (int i = 0; i < 4; i++)
                #pragma unroll
                for (int j = 0; j < 4; j++)
                    o[i][j] += a[i] * bb[j];
        }
        __syncthreads();
    }

    // normalize & write concat-head layout [B,S,D]
    const int b = bh >> 4, h = bh & 15;
    float* ob = g_att + ((long)b * S_ + q0) * D_ + h * DK_;
    #pragma unroll
    for (int i = 0; i < 4; i++) {
        float inv = 1.0f / l_i[i];
        #pragma unroll
        for (int j = 0; j < 4; j++)
            ob[(ty * 4 + i) * D_ + tx * 4 + j] = o[i][j] * inv;
    }
}

// ---------------------------------------------------------------------------
// Output projection: Y[8192x1024] = att[8192x1024] @ Wo^T   (B[k][n] = Wo[n][k])
// ---------------------------------------------------------------------------
__global__ __launch_bounds__(256) void proj_kernel(
    const float* __restrict__ Wo, float* __restrict__ out)
{
    __shared__ float As[16][65];
    __shared__ float Bs[16][65];

    const int n0 = blockIdx.x * 64;
    const int m0 = blockIdx.y * 64;

    const float* Ab = g_att + (long)m0 * D_;

    const int tid = threadIdx.x;
    const int tx  = tid & 15;
    const int ty  = tid >> 4;
    const int ak  = tid & 15, am = tid >> 4;   // A loader
    const int nk  = tid & 15, nn = tid >> 4;   // B loader (k contiguous in Wo rows)

    float acc[4][4] = {};

    for (int k0 = 0; k0 < D_; k0 += 16) {
        #pragma unroll
        for (int i = 0; i < 4; i++)
            As[ak][am + 16 * i] = Ab[(am + 16 * i) * D_ + k0 + ak];
        #pragma unroll
        for (int i = 0; i < 4; i++)
            Bs[nk][nn + 16 * i] = Wo[(long)(n0 + nn + 16 * i) * D_ + k0 + nk];
        __syncthreads();

        #pragma unroll
        for (int kk = 0; kk < 16; kk++) {
            float a[4], bb[4];
            #pragma unroll
            for (int i = 0; i < 4; i++) a[i]  = As[kk][ty * 4 + i];
            #pragma unroll
            for (int j = 0; j < 4; j++) bb[j] = Bs[kk][tx * 4 + j];
            #pragma unroll
            for (int i = 0; i < 4; i++)
                #pragma unroll
                for (int j = 0; j < 4; j++)
                    acc[i][j] += a[i] * bb[j];
        }
        __syncthreads();
    }

    #pragma unroll
    for (int i = 0; i < 4; i++)
        #pragma unroll
        for (int j = 0; j < 4; j++)
            out[(long)(m0 + ty * 4 + i) * D_ + n0 + tx * 4 + j] = acc[i][j];
}

// ---------------------------------------------------------------------------
extern "C" void kernel_launch(void* const* d_in, const int* in_sizes, int n_in,
                              void* d_out, int out_size)
{
    const float* x  = (const float*)d_in[0];
    const float* Wq = (const float*)d_in[1];
    const float* Wk = (const float*)d_in[2];
    const float* Wv = (const float*)d_in[3];
    const float* Wo = (const float*)d_in[4];
    float* out = (float*)d_out;

    // 1) QKV projections: grid (s-tiles, b*h, {q,k,v})
    qkv_kernel<<<dim3(S_ / 64, BH_, 3), 256>>>(x, Wq, Wk, Wv);

    // 2) Flash attention (causal): grid (q-tiles, b*h)
    const size_t shm = (size_t)(64 * 64 + 64 * 65 + 64 * 65 + 64 * 64) * sizeof(float);
    cudaFuncSetAttribute(attn_kernel, cudaFuncAttributeMaxDynamicSharedMemorySize, (int)shm);
    attn_kernel<<<dim3(S_ / 64, BH_), 256, shm>>>();

    // 3) Output projection
    proj_kernel<<<dim3(D_ / 64, (B_ * S_) / 64), 256>>>(Wo, out);
}

// round 3
// speedup vs baseline: 2.4170x; 2.4170x over previous
#include <cuda_runtime.h>
#include <cuda_bf16.h>
#include <math.h>
#include <stdint.h>

// Problem constants
constexpr int S_  = 2048;
constexpr int D_  = 1024;

constexpr float QSCALE = 0.18033688011112042592f;  // 0.125 * log2(e)

// ---------------------------------------------------------------------------
// Scratch (bf16 hi/lo split operands), allocation-free device globals
// q/k/v: [BH=64][S=2048][64]; att/x: [8192][1024]; w: [3072][1024]; wo: [1024][1024]
// ---------------------------------------------------------------------------
__device__ __nv_bfloat16 g_xh[8388608],  g_xl[8388608];
__device__ __nv_bfloat16 g_wh[3145728],  g_wl[3145728];
__device__ __nv_bfloat16 g_woh[1048576], g_wol[1048576];
__device__ __nv_bfloat16 g_qh[8388608],  g_ql[8388608];
__device__ __nv_bfloat16 g_kh[8388608],  g_kl[8388608];
__device__ __nv_bfloat16 g_vh[8388608],  g_vl[8388608];
__device__ __nv_bfloat16 g_atth[8388608], g_attl[8388608];

// ---------------------------------------------------------------------------
// Helpers
// ---------------------------------------------------------------------------
__device__ __forceinline__ void split2(float a, float b, uint32_t& hi, uint32_t& lo) {
    __nv_bfloat162 h = __floats2bfloat162_rn(a, b);
    float ra = a - __bfloat162float(h.x);
    float rb = b - __bfloat162float(h.y);
    __nv_bfloat162 l = __floats2bfloat162_rn(ra, rb);
    hi = *reinterpret_cast<uint32_t*>(&h);
    lo = *reinterpret_cast<uint32_t*>(&l);
}

__device__ __forceinline__ float fast_exp2(float x) {
    float y;
    asm("ex2.approx.ftz.f32 %0, %1;" : "=f"(y) : "f"(x));
    return y;
}

// D(16x8,f32) += A(16x16,bf16,row) * B(16x8,bf16,col)
__device__ __forceinline__ void mma_bf16(float c[4], const uint32_t a[4],
                                         uint32_t b0, uint32_t b1) {
    asm volatile(
        "mma.sync.aligned.m16n8k16.row.col.f32.bf16.bf16.f32 "
        "{%0,%1,%2,%3}, {%4,%5,%6,%7}, {%8,%9}, {%0,%1,%2,%3};"
        : "+f"(c[0]), "+f"(c[1]), "+f"(c[2]), "+f"(c[3])
        : "r"(a[0]), "r"(a[1]), "r"(a[2]), "r"(a[3]), "r"(b0), "r"(b1));
}

// ---------------------------------------------------------------------------
// fp32 -> bf16 hi/lo split (x, Wo)
// ---------------------------------------------------------------------------
__global__ __launch_bounds__(256) void conv_split_kernel(
    const float4* __restrict__ in, uint32_t* __restrict__ oh,
    uint32_t* __restrict__ ol, int n4)
{
    int i = blockIdx.x * blockDim.x + threadIdx.x;
    if (i >= n4) return;
    float4 v = in[i];
    uint32_t h0, l0, h1, l1;
    split2(v.x, v.y, h0, l0);
    split2(v.z, v.w, h1, l1);
    oh[2 * i] = h0; oh[2 * i + 1] = h1;
    ol[2 * i] = l0; ol[2 * i + 1] = l1;
}

// ---------------------------------------------------------------------------
// qkv weight transpose + split: g_wh/g_wl[(sel*1024 + h*64 + kk)][d]
// grid (48 = sel*16+h, 16 d-tiles), block 256
// ---------------------------------------------------------------------------
__global__ __launch_bounds__(256) void wtrans_kernel(
    const float* __restrict__ Wq, const float* __restrict__ Wk,
    const float* __restrict__ Wv)
{
    __shared__ float tile[64][65];
    const int selh = blockIdx.x;
    const int sel  = selh >> 4;
    const int h    = selh & 15;
    const int d0   = blockIdx.y * 64;
    const float* W  = (sel == 0) ? Wq : (sel == 1) ? Wk : Wv;
    const float* Wb = W + (size_t)h * 1024 * 64;

    const int tid = threadIdx.x;
    for (int idx = tid; idx < 64 * 64; idx += 256) {
        int r = idx >> 6, c = idx & 63;               // r: d-offset, c: kk
        tile[r][c] = Wb[(size_t)(d0 + r) * 64 + c];
    }
    __syncthreads();
    const size_t nbase = (size_t)sel * 1024 + h * 64;
    for (int idx = tid; idx < 2048; idx += 256) {
        int r  = idx >> 5;          // kk 0..63
        int c2 = (idx & 31) * 2;    // d-offset (even)
        uint32_t hi, lo;
        split2(tile[c2][r], tile[c2 + 1][r], hi, lo);
        size_t o = (nbase + r) * 1024 + d0 + c2;
        *(uint32_t*)&g_wh[o] = hi;
        *(uint32_t*)&g_wl[o] = lo;
    }
}

// ---------------------------------------------------------------------------
// bf16-split GEMM: C[128x128] = A[m0:+128,:1024] @ B[n0:+128,:1024]^T
// A,B given as hi/lo bf16 [rows][1024] (k contiguous).
// mode 0: qkv epilogue -> scatter split bf16 into g_{q,k,v}{h,l} [BH][S][64],
//         q pre-scaled by QSCALE.
// mode 1: fp32 write to out[m][n] (n-stride 1024).
// ---------------------------------------------------------------------------
__global__ __launch_bounds__(256) void gemm_kernel(
    const __nv_bfloat16* __restrict__ Ah, const __nv_bfloat16* __restrict__ Al,
    const __nv_bfloat16* __restrict__ Bh, const __nv_bfloat16* __restrict__ Bl,
    float* __restrict__ out, int mode)
{
    __shared__ __nv_bfloat16 sAh[128 * 40];
    __shared__ __nv_bfloat16 sAl[128 * 40];
    __shared__ __nv_bfloat16 sBh[128 * 40];
    __shared__ __nv_bfloat16 sBl[128 * 40];

    const int m0 = blockIdx.y * 128;
    const int n0 = blockIdx.x * 128;
    const int tid  = threadIdx.x;
    const int w    = tid >> 5;
    const int lane = tid & 31;
    const int wm = w >> 2;      // 0..1
    const int wn = w & 3;       // 0..3
    const int gr = lane >> 2;   // 0..7
    const int tg = lane & 3;    // 0..3

    float C[4][4][4];
    #pragma unroll
    for (int a = 0; a < 4; a++)
        #pragma unroll
        for (int b = 0; b < 4; b++)
            #pragma unroll
            for (int c = 0; c < 4; c++) C[a][b][c] = 0.0f;

    for (int k0 = 0; k0 < 1024; k0 += 32) {
        // stage tiles (2 uint4 per thread per array)
        #pragma unroll
        for (int i = 0; i < 2; i++) {
            int idx = tid + 256 * i;
            int r = idx >> 2, c = idx & 3;
            size_t ga = (size_t)(m0 + r) * 1024 + k0 + c * 8;
            size_t gb = (size_t)(n0 + r) * 1024 + k0 + c * 8;
            *(uint4*)&sAh[r * 40 + c * 8] = *(const uint4*)(Ah + ga);
            *(uint4*)&sAl[r * 40 + c * 8] = *(const uint4*)(Al + ga);
            *(uint4*)&sBh[r * 40 + c * 8] = *(const uint4*)(Bh + gb);
            *(uint4*)&sBl[r * 40 + c * 8] = *(const uint4*)(Bl + gb);
        }
        __syncthreads();

        #pragma unroll
        for (int ks = 0; ks < 2; ks++) {
            const int col = ks * 16 + tg * 2;
            uint32_t afh[4][4], afl[4][4];
            #pragma unroll
            for (int mf = 0; mf < 4; mf++) {
                int r0 = wm * 64 + mf * 16 + gr;
                afh[mf][0] = *(const uint32_t*)&sAh[(r0    ) * 40 + col    ];
                afh[mf][1] = *(const uint32_t*)&sAh[(r0 + 8) * 40 + col    ];
                afh[mf][2] = *(const uint32_t*)&sAh[(r0    ) * 40 + col + 8];
                afh[mf][3] = *(const uint32_t*)&sAh[(r0 + 8) * 40 + col + 8];
                afl[mf][0] = *(const uint32_t*)&sAl[(r0    ) * 40 + col    ];
                afl[mf][1] = *(const uint32_t*)&sAl[(r0 + 8) * 40 + col    ];
                afl[mf][2] = *(const uint32_t*)&sAl[(r0    ) * 40 + col + 8];
                afl[mf][3] = *(const uint32_t*)&sAl[(r0 + 8) * 40 + col + 8];
            }
            #pragma unroll
            for (int nf = 0; nf < 4; nf++) {
                int n = wn * 32 + nf * 8 + gr;
                uint32_t bh0 = *(const uint32_t*)&sBh[n * 40 + col    ];
                uint32_t bh1 = *(const uint32_t*)&sBh[n * 40 + col + 8];
                uint32_t bl0 = *(const uint32_t*)&sBl[n * 40 + col    ];
                uint32_t bl1 = *(const uint32_t*)&sBl[n * 40 + col + 8];
                #pragma unroll
                for (int mf = 0; mf < 4; mf++) {
                    mma_bf16(C[mf][nf], afh[mf], bh0, bh1);
                    mma_bf16(C[mf][nf], afh[mf], bl0, bl1);
                    mma_bf16(C[mf][nf], afl[mf], bh0, bh1);
                }
            }
        }
        __syncthreads();
    }

    // epilogue
    if (mode == 1) {
        #pragma unroll
        for (int mf = 0; mf < 4; mf++) {
            int row = m0 + wm * 64 + mf * 16 + gr;
            #pragma unroll
            for (int nf = 0; nf < 4; nf++) {
                int col = n0 + wn * 32 + nf * 8 + tg * 2;
                float2 v0 = make_float2(C[mf][nf][0], C[mf][nf][1]);
                float2 v1 = make_float2(C[mf][nf][2], C[mf][nf][3]);
                *(float2*)(out + (size_t)row * 1024 + col)       = v0;
                *(float2*)(out + (size_t)(row + 8) * 1024 + col) = v1;
            }
        }
    } else {
        #pragma unroll
        for (int mf = 0; mf < 4; mf++) {
            int row = m0 + wm * 64 + mf * 16 + gr;
            int b = row >> 11, s = row & 2047;
            #pragma unroll
            for (int nf = 0; nf < 4; nf++) {
                int col = n0 + wn * 32 + nf * 8 + tg * 2;
                int sel = col >> 10;
                int hh  = (col >> 6) & 15;
                int kk  = col & 63;
                __nv_bfloat16* dh = (sel == 0) ? g_qh : (sel == 1) ? g_kh : g_vh;
                __nv_bfloat16* dl = (sel == 0) ? g_ql : (sel == 1) ? g_kl : g_vl;
                float sc = (sel == 0) ? QSCALE : 1.0f;
                size_t i0 = ((size_t)(b * 16 + hh) * 2048 + s) * 64 + kk;
                size_t i1 = i0 + 8 * 64;
                uint32_t hi, lo;
                split2(C[mf][nf][0] * sc, C[mf][nf][1] * sc, hi, lo);
                *(uint32_t*)&dh[i0] = hi;  *(uint32_t*)&dl[i0] = lo;
                split2(C[mf][nf][2] * sc, C[mf][nf][3] * sc, hi, lo);
                *(uint32_t*)&dh[i1] = hi;  *(uint32_t*)&dl[i1] = lo;
            }
        }
    }
}

// ---------------------------------------------------------------------------
// Flash attention (causal) on bf16-split mma. Block: 128 thr (4 warps),
// q-tile 64 (warp w owns rows w*16..+15), kv-tiles of 64, dk=64.
// q pre-scaled by 0.125*log2(e); softmax in base 2.
// ---------------------------------------------------------------------------
__global__ __launch_bounds__(128) void attn_kernel()
{
    __shared__ __nv_bfloat16 sKh[64 * 72];
    __shared__ __nv_bfloat16 sKl[64 * 72];
    __shared__ __nv_bfloat16 sVh[64 * 72];   // transposed: [dk][kv]
    __shared__ __nv_bfloat16 sVl[64 * 72];

    const int q0 = blockIdx.x * 64;
    const int bh = blockIdx.y;
    const int tid  = threadIdx.x;
    const int w    = tid >> 5;
    const int lane = tid & 31;
    const int gr = lane >> 2;
    const int tg = lane & 3;

    const size_t seqbase = (size_t)bh * 2048;

    // --- stage Q (hi->sKh, lo->sKl), load Q frags into regs ---
    {
        const __nv_bfloat16* qh = g_qh + (seqbase + q0) * 64;
        const __nv_bfloat16* ql = g_ql + (seqbase + q0) * 64;
        #pragma unroll
        for (int i = 0; i < 4; i++) {
            int idx = tid + 128 * i;
            int r = idx >> 3, c8 = (idx & 7) * 8;
            *(uint4*)&sKh[r * 72 + c8] = *(const uint4*)(qh + (size_t)r * 64 + c8);
            *(uint4*)&sKl[r * 72 + c8] = *(const uint4*)(ql + (size_t)r * 64 + c8);
        }
    }
    __syncthreads();

    uint32_t Qh[4][4], Ql[4][4];
    {
        const int r0 = w * 16 + gr;
        #pragma unroll
        for (int ks = 0; ks < 4; ks++) {
            int col = ks * 16 + tg * 2;
            Qh[ks][0] = *(const uint32_t*)&sKh[(r0    ) * 72 + col    ];
            Qh[ks][1] = *(const uint32_t*)&sKh[(r0 + 8) * 72 + col    ];
            Qh[ks][2] = *(const uint32_t*)&sKh[(r0    ) * 72 + col + 8];
            Qh[ks][3] = *(const uint32_t*)&sKh[(r0 + 8) * 72 + col + 8];
            Ql[ks][0] = *(const uint32_t*)&sKl[(r0    ) * 72 + col    ];
            Ql[ks][1] = *(const uint32_t*)&sKl[(r0 + 8) * 72 + col    ];
            Ql[ks][2] = *(const uint32_t*)&sKl[(r0    ) * 72 + col + 8];
            Ql[ks][3] = *(const uint32_t*)&sKl[(r0 + 8) * 72 + col + 8];
        }
    }
    __syncthreads();

    float O[8][4];
    #pragma unroll
    for (int nf = 0; nf < 8; nf++)
        #pragma unroll
        for (int c = 0; c < 4; c++) O[nf][c] = 0.0f;
    float m0v = -1e30f, m1v = -1e30f, l0v = 0.0f, l1v = 0.0f;

    for (int kv0 = 0; kv0 <= q0; kv0 += 64) {
        // stage K and transposed V
        {
            const __nv_bfloat16* kh = g_kh + (seqbase + kv0) * 64;
            const __nv_bfloat16* kl = g_kl + (seqbase + kv0) * 64;
            const __nv_bfloat16* vh = g_vh + (seqbase + kv0) * 64;
            const __nv_bfloat16* vl = g_vl + (seqbase + kv0) * 64;
            #pragma unroll
            for (int i = 0; i < 4; i++) {
                int idx = tid + 128 * i;
                int r = idx >> 3, c8 = (idx & 7) * 8;
                *(uint4*)&sKh[r * 72 + c8] = *(const uint4*)(kh + (size_t)r * 64 + c8);
                *(uint4*)&sKl[r * 72 + c8] = *(const uint4*)(kl + (size_t)r * 64 + c8);
                uint4 v4h = *(const uint4*)(vh + (size_t)r * 64 + c8);
                uint4 v4l = *(const uint4*)(vl + (size_t)r * 64 + c8);
                const __nv_bfloat16* ph = (const __nv_bfloat16*)&v4h;
                const __nv_bfloat16* pl = (const __nv_bfloat16*)&v4l;
                #pragma unroll
                for (int j = 0; j < 8; j++) {
                    sVh[(c8 + j) * 72 + r] = ph[j];
                    sVl[(c8 + j) * 72 + r] = pl[j];
                }
            }
        }
        __syncthreads();

        // S = Q @ K^T
        float Sf[8][4];
        #pragma unroll
        for (int nf = 0; nf < 8; nf++)
            #pragma unroll
            for (int c = 0; c < 4; c++) Sf[nf][c] = 0.0f;

        #pragma unroll
        for (int ks = 0; ks < 4; ks++) {
            const int col = ks * 16 + tg * 2;
            #pragma unroll
            for (int nf = 0; nf < 8; nf++) {
                int n = nf * 8 + gr;
                uint32_t kh0 = *(const uint32_t*)&sKh[n * 72 + col    ];
                uint32_t kh1 = *(const uint32_t*)&sKh[n * 72 + col + 8];
                uint32_t kl0 = *(const uint32_t*)&sKl[n * 72 + col    ];
                uint32_t kl1 = *(const uint32_t*)&sKl[n * 72 + col + 8];
                mma_bf16(Sf[nf], Qh[ks], kh0, kh1);
                mma_bf16(Sf[nf], Qh[ks], kl0, kl1);
                mma_bf16(Sf[nf], Ql[ks], kh0, kh1);
            }
        }

        // causal mask (diagonal tile only; kv tile index <= q tile index always)
        if (kv0 == q0) {
            const int row0 = w * 16 + gr;
            #pragma unroll
            for (int nf = 0; nf < 8; nf++) {
                int col = nf * 8 + tg * 2;
                if (col     > row0    ) Sf[nf][0] = -1e30f;
                if (col + 1 > row0    ) Sf[nf][1] = -1e30f;
                if (col     > row0 + 8) Sf[nf][2] = -1e30f;
                if (col + 1 > row0 + 8) Sf[nf][3] = -1e30f;
            }
        }

        // online softmax (base-2)
        float mx0 = -1e30f, mx1 = -1e30f;
        #pragma unroll
        for (int nf = 0; nf < 8; nf++) {
            mx0 = fmaxf(mx0, fmaxf(Sf[nf][0], Sf[nf][1]));
            mx1 = fmaxf(mx1, fmaxf(Sf[nf][2], Sf[nf][3]));
        }
        mx0 = fmaxf(mx0, __shfl_xor_sync(0xffffffffu, mx0, 1));
        mx0 = fmaxf(mx0, __shfl_xor_sync(0xffffffffu, mx0, 2));
        mx1 = fmaxf(mx1, __shfl_xor_sync(0xffffffffu, mx1, 1));
        mx1 = fmaxf(mx1, __shfl_xor_sync(0xffffffffu, mx1, 2));

        float mn0 = fmaxf(m0v, mx0), mn1 = fmaxf(m1v, mx1);
        float a0 = fast_exp2(m0v - mn0), a1 = fast_exp2(m1v - mn1);
        float s0 = 0.0f, s1 = 0.0f;
        #pragma unroll
        for (int nf = 0; nf < 8; nf++) {
            Sf[nf][0] = fast_exp2(Sf[nf][0] - mn0); s0 += Sf[nf][0];
            Sf[nf][1] = fast_exp2(Sf[nf][1] - mn0); s0 += Sf[nf][1];
            Sf[nf][2] = fast_exp2(Sf[nf][2] - mn1); s1 += Sf[nf][2];
            Sf[nf][3] = fast_exp2(Sf[nf][3] - mn1); s1 += Sf[nf][3];
        }
        s0 += __shfl_xor_sync(0xffffffffu, s0, 1);
        s0 += __shfl_xor_sync(0xffffffffu, s0, 2);
        s1 += __shfl_xor_sync(0xffffffffu, s1, 1);
        s1 += __shfl_xor_sync(0xffffffffu, s1, 2);

        l0v = l0v * a0 + s0;  l1v = l1v * a1 + s1;
        m0v = mn0;            m1v = mn1;
        #pragma unroll
        for (int nf = 0; nf < 8; nf++) {
            O[nf][0] *= a0; O[nf][1] *= a0;
            O[nf][2] *= a1; O[nf][3] *= a1;
        }

        // O += P @ V
        #pragma unroll
        for (int ks = 0; ks < 4; ks++) {
            uint32_t Ph[4], Pl[4];
            split2(Sf[2 * ks    ][0], Sf[2 * ks    ][1], Ph[0], Pl[0]);
            split2(Sf[2 * ks    ][2], Sf[2 * ks    ][3], Ph[1], Pl[1]);
            split2(Sf[2 * ks + 1][0], Sf[2 * ks + 1][1], Ph[2], Pl[2]);
            split2(Sf[2 * ks + 1][2], Sf[2 * ks + 1][3], Ph[3], Pl[3]);
            const int col = ks * 16 + tg * 2;
            #pragma unroll
            for (int nf = 0; nf < 8; nf++) {
                int n = nf * 8 + gr;
                uint32_t vh0 = *(const uint32_t*)&sVh[n * 72 + col    ];
                uint32_t vh1 = *(const uint32_t*)&sVh[n * 72 + col + 8];
                uint32_t vl0 = *(const uint32_t*)&sVl[n * 72 + col    ];
                uint32_t vl1 = *(const uint32_t*)&sVl[n * 72 + col + 8];
                mma_bf16(O[nf], Ph, vh0, vh1);
                mma_bf16(O[nf], Ph, vl0, vl1);
                mma_bf16(O[nf], Pl, vh0, vh1);
            }
        }
        __syncthreads();
    }

    // epilogue: normalize and write split bf16 concat-head layout
    const float inv0 = 1.0f / l0v, inv1 = 1.0f / l1v;
    const int b = bh >> 4, h = bh & 15;
    const int row0 = q0 + w * 16 + gr;
    const size_t base0 = ((size_t)(b * 2048) + row0) * 1024 + h * 64;
    const size_t base1 = base0 + (size_t)8 * 1024;
    #pragma unroll
    for (int nf = 0; nf < 8; nf++) {
        int c = nf * 8 + tg * 2;
        uint32_t hi, lo;
        split2(O[nf][0] * inv0, O[nf][1] * inv0, hi, lo);
        *(uint32_t*)&g_atth[base0 + c] = hi;
        *(uint32_t*)&g_attl[base0 + c] = lo;
        split2(O[nf][2] * inv1, O[nf][3] * inv1, hi, lo);
        *(uint32_t*)&g_atth[base1 + c] = hi;
        *(uint32_t*)&g_attl[base1 + c] = lo;
    }
}

// ---------------------------------------------------------------------------
extern "C" void kernel_launch(void* const* d_in, const int* in_sizes, int n_in,
                              void* d_out, int out_size)
{
    const float* x  = (const float*)d_in[0];
    const float* Wq = (const float*)d_in[1];
    const float* Wk = (const float*)d_in[2];
    const float* Wv = (const float*)d_in[3];
    const float* Wo = (const float*)d_in[4];
    float* out = (float*)d_out;

    void *p_xh, *p_xl, *p_wh, *p_wl, *p_woh, *p_wol, *p_atth, *p_attl;
    cudaGetSymbolAddress(&p_xh,  g_xh);   cudaGetSymbolAddress(&p_xl,  g_xl);
    cudaGetSymbolAddress(&p_wh,  g_wh);   cudaGetSymbolAddress(&p_wl,  g_wl);
    cudaGetSymbolAddress(&p_woh, g_woh);  cudaGetSymbolAddress(&p_wol, g_wol);
    cudaGetSymbolAddress(&p_atth, g_atth); cudaGetSymbolAddress(&p_attl, g_attl);

    // 1) split x and Wo into bf16 hi/lo
    conv_split_kernel<<<8192, 256>>>((const float4*)x,
        (uint32_t*)p_xh, (uint32_t*)p_xl, 2097152);
    conv_split_kernel<<<1024, 256>>>((const float4*)Wo,
        (uint32_t*)p_woh, (uint32_t*)p_wol, 262144);

    // 2) transpose+split qkv weights -> [3072][1024]
    wtrans_kernel<<<dim3(48, 16), 256>>>(Wq, Wk, Wv);

    // 3) fused QKV GEMM (bf16-split mma) -> q/k/v split, [BH][S][64]
    gemm_kernel<<<dim3(24, 64), 256>>>(
        (const __nv_bfloat16*)p_xh, (const __nv_bfloat16*)p_xl,
        (const __nv_bfloat16*)p_wh, (const __nv_bfloat16*)p_wl, nullptr, 0);

    // 4) causal flash attention (bf16-split mma) -> att split
    attn_kernel<<<dim3(S_ / 64, 64), 128>>>();

    // 5) output projection -> fp32 out
    gemm_kernel<<<dim3(8, 64), 256>>>(
        (const __nv_bfloat16*)p_atth, (const __nv_bfloat16*)p_attl,
        (const __nv_bfloat16*)p_woh, (const __nv_bfloat16*)p_wol, out, 1);
}

// round 4
// speedup vs baseline: 3.3461x; 1.3844x over previous
#include <cuda_runtime.h>
#include <cuda_bf16.h>
#include <math.h>
#include <stdint.h>

constexpr int S_ = 2048;
constexpr float QSCALE = 0.18033688011112042592f;  // 0.125 * log2(e)

// ---------------------------------------------------------------------------
// Scratch (bf16 hi/lo split), allocation-free device globals
// ---------------------------------------------------------------------------
__device__ __nv_bfloat16 g_xh[8388608],  g_xl[8388608];
__device__ __nv_bfloat16 g_wh[3145728],  g_wl[3145728];
__device__ __nv_bfloat16 g_woh[1048576], g_wol[1048576];
__device__ __nv_bfloat16 g_qh[8388608],  g_ql[8388608];
__device__ __nv_bfloat16 g_kh[8388608],  g_kl[8388608];
__device__ __nv_bfloat16 g_vh[8388608],  g_vl[8388608];
__device__ __nv_bfloat16 g_atth[8388608], g_attl[8388608];

// ---------------------------------------------------------------------------
// Helpers
// ---------------------------------------------------------------------------
__device__ __forceinline__ uint32_t smem_u32(const void* p) {
    uint32_t a;
    asm("{ .reg .u64 t; cvta.to.shared.u64 t, %1; cvt.u32.u64 %0, t; }" : "=r"(a) : "l"(p));
    return a;
}
__device__ __forceinline__ void split2(float a, float b, uint32_t& hi, uint32_t& lo) {
    __nv_bfloat162 h = __floats2bfloat162_rn(a, b);
    float ra = a - __bfloat162float(h.x);
    float rb = b - __bfloat162float(h.y);
    __nv_bfloat162 l = __floats2bfloat162_rn(ra, rb);
    hi = *reinterpret_cast<uint32_t*>(&h);
    lo = *reinterpret_cast<uint32_t*>(&l);
}
__device__ __forceinline__ float fast_exp2(float x) {
    float y;
    asm("ex2.approx.ftz.f32 %0, %1;" : "=f"(y) : "f"(x));
    return y;
}
__device__ __forceinline__ void mma_bf16(float c[4], const uint32_t a[4],
                                         uint32_t b0, uint32_t b1) {
    asm volatile(
        "mma.sync.aligned.m16n8k16.row.col.f32.bf16.bf16.f32 "
        "{%0,%1,%2,%3}, {%4,%5,%6,%7}, {%8,%9}, {%0,%1,%2,%3};"
        : "+f"(c[0]), "+f"(c[1]), "+f"(c[2]), "+f"(c[3])
        : "r"(a[0]), "r"(a[1]), "r"(a[2]), "r"(a[3]), "r"(b0), "r"(b1));
}
__device__ __forceinline__ void cp16(uint32_t s, const void* g) {
    asm volatile("{ .reg .u64 gp; cvta.to.global.u64 gp, %1;"
                 " cp.async.cg.shared.global [%0], [gp], 16; }"
                 :: "r"(s), "l"(g) : "memory");
}
#define CP_COMMIT() asm volatile("cp.async.commit_group;" ::: "memory")
#define CP_WAIT(n)  asm volatile("cp.async.wait_group %0;" :: "n"(n) : "memory")
#define LDSM_X4(R, addr) \
    asm volatile("ldmatrix.sync.aligned.m8n8.x4.shared.b16 {%0,%1,%2,%3}, [%4];" \
        : "=r"((R)[0]), "=r"((R)[1]), "=r"((R)[2]), "=r"((R)[3]) : "r"(addr))
#define LDSM_X4T(R, addr) \
    asm volatile("ldmatrix.sync.aligned.m8n8.x4.trans.shared.b16 {%0,%1,%2,%3}, [%4];" \
        : "=r"((R)[0]), "=r"((R)[1]), "=r"((R)[2]), "=r"((R)[3]) : "r"(addr))

// ---------------------------------------------------------------------------
// fp32 -> bf16 hi/lo split (x, Wo)
// ---------------------------------------------------------------------------
__global__ __launch_bounds__(256) void conv_split_kernel(
    const float4* __restrict__ in, uint32_t* __restrict__ oh,
    uint32_t* __restrict__ ol, int n4)
{
    int i = blockIdx.x * blockDim.x + threadIdx.x;
    if (i >= n4) return;
    float4 v = in[i];
    uint32_t h0, l0, h1, l1;
    split2(v.x, v.y, h0, l0);
    split2(v.z, v.w, h1, l1);
    oh[2 * i] = h0; oh[2 * i + 1] = h1;
    ol[2 * i] = l0; ol[2 * i + 1] = l1;
}

// ---------------------------------------------------------------------------
// qkv weight transpose + split
// ---------------------------------------------------------------------------
__global__ __launch_bounds__(256) void wtrans_kernel(
    const float* __restrict__ Wq, const float* __restrict__ Wk,
    const float* __restrict__ Wv)
{
    __shared__ float tile[64][65];
    const int selh = blockIdx.x;
    const int sel  = selh >> 4;
    const int h    = selh & 15;
    const int d0   = blockIdx.y * 64;
    const float* W  = (sel == 0) ? Wq : (sel == 1) ? Wk : Wv;
    const float* Wb = W + (size_t)h * 1024 * 64;

    const int tid = threadIdx.x;
    for (int idx = tid; idx < 64 * 64; idx += 256) {
        int r = idx >> 6, c = idx & 63;
        tile[r][c] = Wb[(size_t)(d0 + r) * 64 + c];
    }
    __syncthreads();
    const size_t nbase = (size_t)sel * 1024 + h * 64;
    for (int idx = tid; idx < 2048; idx += 256) {
        int r  = idx >> 5;
        int c2 = (idx & 31) * 2;
        uint32_t hi, lo;
        split2(tile[c2][r], tile[c2 + 1][r], hi, lo);
        size_t o = (nbase + r) * 1024 + d0 + c2;
        *(uint32_t*)&g_wh[o] = hi;
        *(uint32_t*)&g_wl[o] = lo;
    }
}

// ---------------------------------------------------------------------------
// bf16-split GEMM, cp.async double-buffered, ldmatrix frags.
// C[128x128] = A[m0:+128,:1024] @ B[n0:+128,:1024]^T
// mode 0: scatter split bf16 q/k/v (q scaled); mode 1: fp32 out.
// ---------------------------------------------------------------------------
__global__ __launch_bounds__(256) void gemm_kernel(
    const __nv_bfloat16* __restrict__ Ah, const __nv_bfloat16* __restrict__ Al,
    const __nv_bfloat16* __restrict__ Bh, const __nv_bfloat16* __restrict__ Bl,
    float* __restrict__ out, int mode)
{
    extern __shared__ __nv_bfloat16 dsm[];
    // stage layout (bytes): [Ah 10240][Al 10240][Bh 10240][Bl 10240] x 2 stages
    constexpr uint32_t ARR = 10240, STG = 40960;

    const int m0 = blockIdx.y * 128;
    const int n0 = blockIdx.x * 128;
    const int tid = threadIdx.x;
    const int w = tid >> 5, lane = tid & 31;
    const int wm = w >> 2, wn = w & 3;
    const int gr = lane >> 2, tg = lane & 3;
    const uint32_t sbase = smem_u32(dsm);

    float C[4][4][4];
    #pragma unroll
    for (int a = 0; a < 4; a++)
        #pragma unroll
        for (int b = 0; b < 4; b++)
            #pragma unroll
            for (int c = 0; c < 4; c++) C[a][b][c] = 0.0f;

    const uint32_t a_rowb = (uint32_t)(wm * 64 + (lane & 7) + ((lane & 8) ? 8 : 0));
    const uint32_t a_coff = (lane & 16) ? 8 : 0;
    const uint32_t b_rowb = (uint32_t)(wn * 32 + (lane & 7) + ((lane & 16) ? 8 : 0));
    const uint32_t b_coff = (lane & 8) ? 8 : 0;

    auto stage_load = [&](int it, int buf) {
        const int k0 = it * 32;
        const uint32_t sa = sbase + (uint32_t)buf * STG;
        #pragma unroll
        for (int i = 0; i < 2; i++) {
            const int row = (tid >> 2) + 64 * i;
            const int c4  = tid & 3;
            const uint32_t so = (uint32_t)(row * 80 + c4 * 16);
            const size_t goA = (size_t)(m0 + row) * 1024 + k0 + c4 * 8;
            const size_t goB = (size_t)(n0 + row) * 1024 + k0 + c4 * 8;
            cp16(sa + so,           Ah + goA);
            cp16(sa + ARR + so,     Al + goA);
            cp16(sa + 2 * ARR + so, Bh + goB);
            cp16(sa + 3 * ARR + so, Bl + goB);
        }
        CP_COMMIT();
    };

    stage_load(0, 0);
    for (int it = 0; it < 32; it++) {
        const int buf = it & 1;
        if (it + 1 < 32) { stage_load(it + 1, 1 - buf); CP_WAIT(1); }
        else             { CP_WAIT(0); }
        __syncthreads();
        const uint32_t sa = sbase + (uint32_t)buf * STG;

        #pragma unroll
        for (int ks = 0; ks < 2; ks++) {
            const uint32_t acol = (uint32_t)(ks * 16) + a_coff;
            const uint32_t bcol = (uint32_t)(ks * 16) + b_coff;
            uint32_t ah[4][4], al[4][4];
            #pragma unroll
            for (int mf = 0; mf < 4; mf++) {
                uint32_t ad = sa + (a_rowb + mf * 16) * 80 + acol * 2;
                LDSM_X4(ah[mf], ad);
                LDSM_X4(al[mf], ad + ARR);
            }
            uint32_t bhf[4][2], blf[4][2];
            #pragma unroll
            for (int np = 0; np < 2; np++) {
                uint32_t bd = sa + 2 * ARR + (b_rowb + np * 16) * 80 + bcol * 2;
                uint32_t r[4];
                LDSM_X4(r, bd);
                bhf[np * 2][0] = r[0]; bhf[np * 2][1] = r[1];
                bhf[np * 2 + 1][0] = r[2]; bhf[np * 2 + 1][1] = r[3];
                LDSM_X4(r, bd + ARR);
                blf[np * 2][0] = r[0]; blf[np * 2][1] = r[1];
                blf[np * 2 + 1][0] = r[2]; blf[np * 2 + 1][1] = r[3];
            }
            #pragma unroll
            for (int mf = 0; mf < 4; mf++)
                #pragma unroll
                for (int nf = 0; nf < 4; nf++) {
                    mma_bf16(C[mf][nf], ah[mf], bhf[nf][0], bhf[nf][1]);
                    mma_bf16(C[mf][nf], ah[mf], blf[nf][0], blf[nf][1]);
                    mma_bf16(C[mf][nf], al[mf], bhf[nf][0], bhf[nf][1]);
                }
        }
        __syncthreads();
    }

    if (mode == 1) {
        #pragma unroll
        for (int mf = 0; mf < 4; mf++) {
            int row = m0 + wm * 64 + mf * 16 + gr;
            #pragma unroll
            for (int nf = 0; nf < 4; nf++) {
                int col = n0 + wn * 32 + nf * 8 + tg * 2;
                *(float2*)(out + (size_t)row * 1024 + col) =
                    make_float2(C[mf][nf][0], C[mf][nf][1]);
                *(float2*)(out + (size_t)(row + 8) * 1024 + col) =
                    make_float2(C[mf][nf][2], C[mf][nf][3]);
            }
        }
    } else {
        #pragma unroll
        for (int mf = 0; mf < 4; mf++) {
            int row = m0 + wm * 64 + mf * 16 + gr;
            int b = row >> 11, s = row & 2047;
            #pragma unroll
            for (int nf = 0; nf < 4; nf++) {
                int col = n0 + wn * 32 + nf * 8 + tg * 2;
                int sel = col >> 10;
                int hh  = (col >> 6) & 15;
                int kk  = col & 63;
                __nv_bfloat16* dh = (sel == 0) ? g_qh : (sel == 1) ? g_kh : g_vh;
                __nv_bfloat16* dl = (sel == 0) ? g_ql : (sel == 1) ? g_kl : g_vl;
                float sc = (sel == 0) ? QSCALE : 1.0f;
                size_t i0 = ((size_t)(b * 16 + hh) * 2048 + s) * 64 + kk;
                size_t i1 = i0 + 8 * 64;
                uint32_t hi, lo;
                split2(C[mf][nf][0] * sc, C[mf][nf][1] * sc, hi, lo);
                *(uint32_t*)&dh[i0] = hi;  *(uint32_t*)&dl[i0] = lo;
                split2(C[mf][nf][2] * sc, C[mf][nf][3] * sc, hi, lo);
                *(uint32_t*)&dh[i1] = hi;  *(uint32_t*)&dl[i1] = lo;
            }
        }
    }
}

// ---------------------------------------------------------------------------
// Flash attention (causal), 256 thr, q-tile 128 (warp w: rows w*16..+15),
// kv-tiles 64, cp.async double-buffered K/V, ldmatrix(.trans for V).
// dyn smem: 2 stages x [Kh Kl Vh Vl](64x72) + Q (128x72 hi,lo)
// ---------------------------------------------------------------------------
__global__ __launch_bounds__(256) void attn_kernel()
{
    extern __shared__ __nv_bfloat16 dsm[];
    constexpr uint32_t KARR = 9216, KSTG = 36864, QOFF = 73728, QARR = 18432;

    const int qb = (int)gridDim.x - 1 - (int)blockIdx.x;  // heavy blocks first
    const int q0 = qb * 128;
    const int bh = blockIdx.y;
    const int tid = threadIdx.x;
    const int w = tid >> 5, lane = tid & 31;
    const int gr = lane >> 2, tg = lane & 3;
    const size_t seqbase = (size_t)bh * 2048;
    const uint32_t sbase = smem_u32(dsm);

    // stage Q (once)
    {
        const __nv_bfloat16* qh = g_qh + (seqbase + q0) * 64;
        const __nv_bfloat16* ql = g_ql + (seqbase + q0) * 64;
        #pragma unroll
        for (int i = 0; i < 4; i++) {
            int c = tid + 256 * i;
            int row = c >> 3, c8 = c & 7;
            uint32_t so = (uint32_t)(row * 144 + c8 * 16);
            size_t go = (size_t)row * 64 + c8 * 8;
            cp16(sbase + QOFF + so,        qh + go);
            cp16(sbase + QOFF + QARR + so, ql + go);
        }
        CP_COMMIT();
    }

    auto stage_kv = [&](int it, int buf) {
        const int kv0 = it * 64;
        const uint32_t sa = sbase + (uint32_t)buf * KSTG;
        const __nv_bfloat16* kh = g_kh + (seqbase + kv0) * 64;
        const __nv_bfloat16* kl = g_kl + (seqbase + kv0) * 64;
        const __nv_bfloat16* vh = g_vh + (seqbase + kv0) * 64;
        const __nv_bfloat16* vl = g_vl + (seqbase + kv0) * 64;
        #pragma unroll
        for (int i = 0; i < 2; i++) {
            int c = tid + 256 * i;
            int row = c >> 3, c8 = c & 7;
            uint32_t so = (uint32_t)(row * 144 + c8 * 16);
            size_t go = (size_t)row * 64 + c8 * 8;
            cp16(sa + so,            kh + go);
            cp16(sa + KARR + so,     kl + go);
            cp16(sa + 2 * KARR + so, vh + go);
            cp16(sa + 3 * KARR + so, vl + go);
        }
        CP_COMMIT();
    };

    const int nt = qb * 2 + 2;
    stage_kv(0, 0);
    CP_WAIT(1);            // Q group complete (kv0 may be pending)
    __syncthreads();

    // Q frags
    uint32_t Qh[4][4], Ql[4][4];
    {
        const uint32_t q_rowb = (uint32_t)(w * 16 + (lane & 7) + ((lane & 8) ? 8 : 0));
        const uint32_t q_coff = (lane & 16) ? 8 : 0;
        #pragma unroll
        for (int ks = 0; ks < 4; ks++) {
            uint32_t ad = sbase + QOFF + q_rowb * 144 + (ks * 16 + q_coff) * 2;
            LDSM_X4(Qh[ks], ad);
            LDSM_X4(Ql[ks], ad + QARR);
        }
    }

    float O[8][4];
    #pragma unroll
    for (int nf = 0; nf < 8; nf++)
        #pragma unroll
        for (int c = 0; c < 4; c++) O[nf][c] = 0.0f;
    float m0v = -1e30f, m1v = -1e30f, l0v = 0.0f, l1v = 0.0f;
    const int wrow = q0 + w * 16;

    const uint32_t k_rowb = (uint32_t)((lane & 7) + ((lane & 16) ? 8 : 0));
    const uint32_t k_coff = (lane & 8) ? 8 : 0;
    const uint32_t v_coff = (lane & 16) ? 8 : 0;

    for (int it = 0; it < nt; it++) {
        const int buf = it & 1;
        if (it + 1 < nt) { stage_kv(it + 1, 1 - buf); CP_WAIT(1); }
        else             { CP_WAIT(0); }
        __syncthreads();
        const int kv0 = it * 64;

        if (kv0 <= wrow + 15) {
            const uint32_t sa = sbase + (uint32_t)buf * KSTG;

            // S = Q @ K^T
            float Sf[8][4];
            #pragma unroll
            for (int nf = 0; nf < 8; nf++)
                #pragma unroll
                for (int c = 0; c < 4; c++) Sf[nf][c] = 0.0f;

            #pragma unroll
            for (int ks = 0; ks < 4; ks++) {
                const uint32_t kcol = (uint32_t)(ks * 16) + k_coff;
                #pragma unroll
                for (int np = 0; np < 4; np++) {
                    uint32_t bd = sa + (k_rowb + np * 16) * 144 + kcol * 2;
                    uint32_t rh[4], rl[4];
                    LDSM_X4(rh, bd);
                    LDSM_X4(rl, bd + KARR);
                    mma_bf16(Sf[np * 2],     Qh[ks], rh[0], rh[1]);
                    mma_bf16(Sf[np * 2],     Qh[ks], rl[0], rl[1]);
                    mma_bf16(Sf[np * 2],     Ql[ks], rh[0], rh[1]);
                    mma_bf16(Sf[np * 2 + 1], Qh[ks], rh[2], rh[3]);
                    mma_bf16(Sf[np * 2 + 1], Qh[ks], rl[2], rl[3]);
                    mma_bf16(Sf[np * 2 + 1], Ql[ks], rh[2], rh[3]);
                }
            }

            // causal mask (boundary tiles only)
            if (kv0 + 63 > wrow) {
                const int r0g = wrow + gr;
                #pragma unroll
                for (int nf = 0; nf < 8; nf++) {
                    int col = kv0 + nf * 8 + tg * 2;
                    if (col     > r0g)     Sf[nf][0] = -1e30f;
                    if (col + 1 > r0g)     Sf[nf][1] = -1e30f;
                    if (col     > r0g + 8) Sf[nf][2] = -1e30f;
                    if (col + 1 > r0g + 8) Sf[nf][3] = -1e30f;
                }
            }

            // online softmax (base-2; q pre-scaled)
            float mx0 = -1e30f, mx1 = -1e30f;
            #pragma unroll
            for (int nf = 0; nf < 8; nf++) {
                mx0 = fmaxf(mx0, fmaxf(Sf[nf][0], Sf[nf][1]));
                mx1 = fmaxf(mx1, fmaxf(Sf[nf][2], Sf[nf][3]));
            }
            mx0 = fmaxf(mx0, __shfl_xor_sync(0xffffffffu, mx0, 1));
            mx0 = fmaxf(mx0, __shfl_xor_sync(0xffffffffu, mx0, 2));
            mx1 = fmaxf(mx1, __shfl_xor_sync(0xffffffffu, mx1, 1));
            mx1 = fmaxf(mx1, __shfl_xor_sync(0xffffffffu, mx1, 2));

            float mn0 = fmaxf(m0v, mx0), mn1 = fmaxf(m1v, mx1);
            float a0 = fast_exp2(m0v - mn0), a1 = fast_exp2(m1v - mn1);
            float s0 = 0.0f, s1 = 0.0f;
            #pragma unroll
            for (int nf = 0; nf < 8; nf++) {
                Sf[nf][0] = fast_exp2(Sf[nf][0] - mn0); s0 += Sf[nf][0];
                Sf[nf][1] = fast_exp2(Sf[nf][1] - mn0); s0 += Sf[nf][1];
                Sf[nf][2] = fast_exp2(Sf[nf][2] - mn1); s1 += Sf[nf][2];
                Sf[nf][3] = fast_exp2(Sf[nf][3] - mn1); s1 += Sf[nf][3];
            }
            s0 += __shfl_xor_sync(0xffffffffu, s0, 1);
            s0 += __shfl_xor_sync(0xffffffffu, s0, 2);
            s1 += __shfl_xor_sync(0xffffffffu, s1, 1);
            s1 += __shfl_xor_sync(0xffffffffu, s1, 2);

            l0v = l0v * a0 + s0;  l1v = l1v * a1 + s1;
            m0v = mn0;            m1v = mn1;
            #pragma unroll
            for (int nf = 0; nf < 8; nf++) {
                O[nf][0] *= a0; O[nf][1] *= a0;
                O[nf][2] *= a1; O[nf][3] *= a1;
            }

            // O += P @ V   (V row-major in smem; ldmatrix.trans)
            #pragma unroll
            for (int ks = 0; ks < 4; ks++) {
                uint32_t Ph[4], Pl[4];
                split2(Sf[2 * ks][0],     Sf[2 * ks][1],     Ph[0], Pl[0]);
                split2(Sf[2 * ks][2],     Sf[2 * ks][3],     Ph[1], Pl[1]);
                split2(Sf[2 * ks + 1][0], Sf[2 * ks + 1][1], Ph[2], Pl[2]);
                split2(Sf[2 * ks + 1][2], Sf[2 * ks + 1][3], Ph[3], Pl[3]);
                const uint32_t v_rowb = (uint32_t)(ks * 16 + (lane & 15));
                #pragma unroll
                for (int np = 0; np < 4; np++) {
                    uint32_t vd = sa + 2 * KARR + v_rowb * 144
                                + ((uint32_t)(np * 16) + v_coff) * 2;
                    uint32_t rh[4], rl[4];
                    LDSM_X4T(rh, vd);
                    LDSM_X4T(rl, vd + KARR);
                    mma_bf16(O[np * 2],     Ph, rh[0], rh[1]);
                    mma_bf16(O[np * 2],     Ph, rl[0], rl[1]);
                    mma_bf16(O[np * 2],     Pl, rh[0], rh[1]);
                    mma_bf16(O[np * 2 + 1], Ph, rh[2], rh[3]);
                    mma_bf16(O[np * 2 + 1], Ph, rl[2], rl[3]);
                    mma_bf16(O[np * 2 + 1], Pl, rh[2], rh[3]);
                }
            }
        }
        __syncthreads();
    }

    // epilogue: normalize, split, write concat-head layout
    const float inv0 = 1.0f / l0v, inv1 = 1.0f / l1v;
    const int b = bh >> 4, h = bh & 15;
    const int row0 = q0 + w * 16 + gr;
    const size_t base0 = ((size_t)(b * 2048) + row0) * 1024 + h * 64;
    const size_t base1 = base0 + (size_t)8 * 1024;
    #pragma unroll
    for (int nf = 0; nf < 8; nf++) {
        int c = nf * 8 + tg * 2;
        uint32_t hi, lo;
        split2(O[nf][0] * inv0, O[nf][1] * inv0, hi, lo);
        *(uint32_t*)&g_atth[base0 + c] = hi;
        *(uint32_t*)&g_attl[base0 + c] = lo;
        split2(O[nf][2] * inv1, O[nf][3] * inv1, hi, lo);
        *(uint32_t*)&g_atth[base1 + c] = hi;
        *(uint32_t*)&g_attl[base1 + c] = lo;
    }
}

// ---------------------------------------------------------------------------
extern "C" void kernel_launch(void* const* d_in, const int* in_sizes, int n_in,
                              void* d_out, int out_size)
{
    const float* x  = (const float*)d_in[0];
    const float* Wq = (const float*)d_in[1];
    const float* Wk = (const float*)d_in[2];
    const float* Wv = (const float*)d_in[3];
    const float* Wo = (const float*)d_in[4];
    float* out = (float*)d_out;

    void *p_xh, *p_xl, *p_wh, *p_wl, *p_woh, *p_wol, *p_atth, *p_attl;
    cudaGetSymbolAddress(&p_xh,  g_xh);   cudaGetSymbolAddress(&p_xl,  g_xl);
    cudaGetSymbolAddress(&p_wh,  g_wh);   cudaGetSymbolAddress(&p_wl,  g_wl);
    cudaGetSymbolAddress(&p_woh, g_woh);  cudaGetSymbolAddress(&p_wol, g_wol);
    cudaGetSymbolAddress(&p_atth, g_atth); cudaGetSymbolAddress(&p_attl, g_attl);

    const int gemm_shm = 81920;
    const int attn_shm = 110592;
    cudaFuncSetAttribute(gemm_kernel, cudaFuncAttributeMaxDynamicSharedMemorySize, gemm_shm);
    cudaFuncSetAttribute(attn_kernel, cudaFuncAttributeMaxDynamicSharedMemorySize, attn_shm);

    conv_split_kernel<<<8192, 256>>>((const float4*)x,
        (uint32_t*)p_xh, (uint32_t*)p_xl, 2097152);
    conv_split_kernel<<<1024, 256>>>((const float4*)Wo,
        (uint32_t*)p_woh, (uint32_t*)p_wol, 262144);

    wtrans_kernel<<<dim3(48, 16), 256>>>(Wq, Wk, Wv);

    gemm_kernel<<<dim3(24, 64), 256, gemm_shm>>>(
        (const __nv_bfloat16*)p_xh, (const __nv_bfloat16*)p_xl,
        (const __nv_bfloat16*)p_wh, (const __nv_bfloat16*)p_wl, nullptr, 0);

    attn_kernel<<<dim3(S_ / 128, 64), 256, attn_shm>>>();

    gemm_kernel<<<dim3(8, 64), 256, gemm_shm>>>(
        (const __nv_bfloat16*)p_atth, (const __nv_bfloat16*)p_attl,
        (const __nv_bfloat16*)p_woh, (const __nv_bfloat16*)p_wol, out, 1);
}

// round 5
// speedup vs baseline: 3.6895x; 1.1027x over previous
#include <cuda_runtime.h>
#include <cuda_bf16.h>
#include <math.h>
#include <stdint.h>

constexpr int S_ = 2048;
constexpr float QSCALE = 0.18033688011112042592f;  // 0.125 * log2(e)

// ---------------------------------------------------------------------------
// Scratch (bf16 hi/lo split), allocation-free device globals
// ---------------------------------------------------------------------------
__device__ __nv_bfloat16 g_xh[8388608],  g_xl[8388608];
__device__ __nv_bfloat16 g_wh[3145728],  g_wl[3145728];
__device__ __nv_bfloat16 g_woh[1048576], g_wol[1048576];
__device__ __nv_bfloat16 g_qh[8388608],  g_ql[8388608];
__device__ __nv_bfloat16 g_kh[8388608],  g_kl[8388608];
__device__ __nv_bfloat16 g_vh[8388608],  g_vl[8388608];
__device__ __nv_bfloat16 g_atth[8388608], g_attl[8388608];

// ---------------------------------------------------------------------------
// Helpers
// ---------------------------------------------------------------------------
__device__ __forceinline__ uint32_t smem_u32(const void* p) {
    uint32_t a;
    asm("{ .reg .u64 t; cvta.to.shared.u64 t, %1; cvt.u32.u64 %0, t; }" : "=r"(a) : "l"(p));
    return a;
}
__device__ __forceinline__ void split2(float a, float b, uint32_t& hi, uint32_t& lo) {
    __nv_bfloat162 h = __floats2bfloat162_rn(a, b);
    float ra = a - __bfloat162float(h.x);
    float rb = b - __bfloat162float(h.y);
    __nv_bfloat162 l = __floats2bfloat162_rn(ra, rb);
    hi = *reinterpret_cast<uint32_t*>(&h);
    lo = *reinterpret_cast<uint32_t*>(&l);
}
__device__ __forceinline__ float fast_exp2(float x) {
    float y;
    asm("ex2.approx.ftz.f32 %0, %1;" : "=f"(y) : "f"(x));
    return y;
}
__device__ __forceinline__ void mma_bf16(float c[4], const uint32_t a[4],
                                         uint32_t b0, uint32_t b1) {
    asm volatile(
        "mma.sync.aligned.m16n8k16.row.col.f32.bf16.bf16.f32 "
        "{%0,%1,%2,%3}, {%4,%5,%6,%7}, {%8,%9}, {%0,%1,%2,%3};"
        : "+f"(c[0]), "+f"(c[1]), "+f"(c[2]), "+f"(c[3])
        : "r"(a[0]), "r"(a[1]), "r"(a[2]), "r"(a[3]), "r"(b0), "r"(b1));
}
__device__ __forceinline__ void cp16(uint32_t s, const void* g) {
    asm volatile("{ .reg .u64 gp; cvta.to.global.u64 gp, %1;"
                 " cp.async.cg.shared.global [%0], [gp], 16; }"
                 :: "r"(s), "l"(g) : "memory");
}
#define CP_COMMIT() asm volatile("cp.async.commit_group;" ::: "memory")
#define CP_WAIT(n)  asm volatile("cp.async.wait_group %0;" :: "n"(n) : "memory")
#define LDSM_X4(R, addr) \
    asm volatile("ldmatrix.sync.aligned.m8n8.x4.shared.b16 {%0,%1,%2,%3}, [%4];" \
        : "=r"((R)[0]), "=r"((R)[1]), "=r"((R)[2]), "=r"((R)[3]) : "r"(addr))
#define LDSM_X4T(R, addr) \
    asm volatile("ldmatrix.sync.aligned.m8n8.x4.trans.shared.b16 {%0,%1,%2,%3}, [%4];" \
        : "=r"((R)[0]), "=r"((R)[1]), "=r"((R)[2]), "=r"((R)[3]) : "r"(addr))

// ---------------------------------------------------------------------------
// fp32 -> bf16 hi/lo split (x, Wo)
// ---------------------------------------------------------------------------
__global__ __launch_bounds__(256) void conv_split_kernel(
    const float4* __restrict__ in, uint32_t* __restrict__ oh,
    uint32_t* __restrict__ ol, int n4)
{
    int i = blockIdx.x * blockDim.x + threadIdx.x;
    if (i >= n4) return;
    float4 v = in[i];
    uint32_t h0, l0, h1, l1;
    split2(v.x, v.y, h0, l0);
    split2(v.z, v.w, h1, l1);
    oh[2 * i] = h0; oh[2 * i + 1] = h1;
    ol[2 * i] = l0; ol[2 * i + 1] = l1;
}

// ---------------------------------------------------------------------------
// qkv weight transpose + split
// ---------------------------------------------------------------------------
__global__ __launch_bounds__(256) void wtrans_kernel(
    const float* __restrict__ Wq, const float* __restrict__ Wk,
    const float* __restrict__ Wv)
{
    __shared__ float tile[64][65];
    const int selh = blockIdx.x;
    const int sel  = selh >> 4;
    const int h    = selh & 15;
    const int d0   = blockIdx.y * 64;
    const float* W  = (sel == 0) ? Wq : (sel == 1) ? Wk : Wv;
    const float* Wb = W + (size_t)h * 1024 * 64;

    const int tid = threadIdx.x;
    for (int idx = tid; idx < 64 * 64; idx += 256) {
        int r = idx >> 6, c = idx & 63;
        tile[r][c] = Wb[(size_t)(d0 + r) * 64 + c];
    }
    __syncthreads();
    const size_t nbase = (size_t)sel * 1024 + h * 64;
    for (int idx = tid; idx < 2048; idx += 256) {
        int r  = idx >> 5;
        int c2 = (idx & 31) * 2;
        uint32_t hi, lo;
        split2(tile[c2][r], tile[c2 + 1][r], hi, lo);
        size_t o = (nbase + r) * 1024 + d0 + c2;
        *(uint32_t*)&g_wh[o] = hi;
        *(uint32_t*)&g_wl[o] = lo;
    }
}

// ---------------------------------------------------------------------------
// bf16-split GEMM, cp.async double-buffered, ldmatrix frags, 2 CTAs/SM.
// C[128x128] = A[m0:+128,:1024] @ B[n0:+128,:1024]^T
// mode 0: scatter split bf16 q/k/v (q scaled); mode 1: fp32 out.
// ---------------------------------------------------------------------------
__global__ __launch_bounds__(256, 2) void gemm_kernel(
    const __nv_bfloat16* __restrict__ Ah, const __nv_bfloat16* __restrict__ Al,
    const __nv_bfloat16* __restrict__ Bh, const __nv_bfloat16* __restrict__ Bl,
    float* __restrict__ out, int mode)
{
    extern __shared__ __nv_bfloat16 dsm[];
    constexpr uint32_t ARR = 10240, STG = 40960;

    const int m0 = blockIdx.y * 128;
    const int n0 = blockIdx.x * 128;
    const int tid = threadIdx.x;
    const int w = tid >> 5, lane = tid & 31;
    const int wm = w >> 2, wn = w & 3;
    const int gr = lane >> 2, tg = lane & 3;
    const uint32_t sbase = smem_u32(dsm);

    float C[4][4][4];
    #pragma unroll
    for (int a = 0; a < 4; a++)
        #pragma unroll
        for (int b = 0; b < 4; b++)
            #pragma unroll
            for (int c = 0; c < 4; c++) C[a][b][c] = 0.0f;

    const uint32_t a_rowb = (uint32_t)(wm * 64 + (lane & 7) + ((lane & 8) ? 8 : 0));
    const uint32_t a_coff = (lane & 16) ? 8 : 0;
    const uint32_t b_rowb = (uint32_t)(wn * 32 + (lane & 7) + ((lane & 16) ? 8 : 0));
    const uint32_t b_coff = (lane & 8) ? 8 : 0;

    auto stage_load = [&](int it, int buf) {
        const int k0 = it * 32;
        const uint32_t sa = sbase + (uint32_t)buf * STG;
        #pragma unroll
        for (int i = 0; i < 2; i++) {
            const int row = (tid >> 2) + 64 * i;
            const int c4  = tid & 3;
            const uint32_t so = (uint32_t)(row * 80 + c4 * 16);
            const size_t goA = (size_t)(m0 + row) * 1024 + k0 + c4 * 8;
            const size_t goB = (size_t)(n0 + row) * 1024 + k0 + c4 * 8;
            cp16(sa + so,           Ah + goA);
            cp16(sa + ARR + so,     Al + goA);
            cp16(sa + 2 * ARR + so, Bh + goB);
            cp16(sa + 3 * ARR + so, Bl + goB);
        }
        CP_COMMIT();
    };

    stage_load(0, 0);
    for (int it = 0; it < 32; it++) {
        const int buf = it & 1;
        if (it + 1 < 32) { stage_load(it + 1, 1 - buf); CP_WAIT(1); }
        else             { CP_WAIT(0); }
        __syncthreads();
        const uint32_t sa = sbase + (uint32_t)buf * STG;

        #pragma unroll
        for (int ks = 0; ks < 2; ks++) {
            const uint32_t acol = (uint32_t)(ks * 16) + a_coff;
            const uint32_t bcol = (uint32_t)(ks * 16) + b_coff;
            uint32_t ah[4][4], al[4][4];
            #pragma unroll
            for (int mf = 0; mf < 4; mf++) {
                uint32_t ad = sa + (a_rowb + mf * 16) * 80 + acol * 2;
                LDSM_X4(ah[mf], ad);
                LDSM_X4(al[mf], ad + ARR);
            }
            uint32_t bhf[4][2], blf[4][2];
            #pragma unroll
            for (int np = 0; np < 2; np++) {
                uint32_t bd = sa + 2 * ARR + (b_rowb + np * 16) * 80 + bcol * 2;
                uint32_t r[4];
                LDSM_X4(r, bd);
                bhf[np * 2][0] = r[0]; bhf[np * 2][1] = r[1];
                bhf[np * 2 + 1][0] = r[2]; bhf[np * 2 + 1][1] = r[3];
                LDSM_X4(r, bd + ARR);
                blf[np * 2][0] = r[0]; blf[np * 2][1] = r[1];
                blf[np * 2 + 1][0] = r[2]; blf[np * 2 + 1][1] = r[3];
            }
            #pragma unroll
            for (int mf = 0; mf < 4; mf++)
                #pragma unroll
                for (int nf = 0; nf < 4; nf++) {
                    mma_bf16(C[mf][nf], ah[mf], bhf[nf][0], bhf[nf][1]);
                    mma_bf16(C[mf][nf], ah[mf], blf[nf][0], blf[nf][1]);
                    mma_bf16(C[mf][nf], al[mf], bhf[nf][0], bhf[nf][1]);
                }
        }
        __syncthreads();
    }

    if (mode == 1) {
        #pragma unroll
        for (int mf = 0; mf < 4; mf++) {
            int row = m0 + wm * 64 + mf * 16 + gr;
            #pragma unroll
            for (int nf = 0; nf < 4; nf++) {
                int col = n0 + wn * 32 + nf * 8 + tg * 2;
                *(float2*)(out + (size_t)row * 1024 + col) =
                    make_float2(C[mf][nf][0], C[mf][nf][1]);
                *(float2*)(out + (size_t)(row + 8) * 1024 + col) =
                    make_float2(C[mf][nf][2], C[mf][nf][3]);
            }
        }
    } else {
        #pragma unroll
        for (int mf = 0; mf < 4; mf++) {
            int row = m0 + wm * 64 + mf * 16 + gr;
            int b = row >> 11, s = row & 2047;
            #pragma unroll
            for (int nf = 0; nf < 4; nf++) {
                int col = n0 + wn * 32 + nf * 8 + tg * 2;
                int sel = col >> 10;
                int hh  = (col >> 6) & 15;
                int kk  = col & 63;
                __nv_bfloat16* dh = (sel == 0) ? g_qh : (sel == 1) ? g_kh : g_vh;
                __nv_bfloat16* dl = (sel == 0) ? g_ql : (sel == 1) ? g_kl : g_vl;
                float sc = (sel == 0) ? QSCALE : 1.0f;
                size_t i0 = ((size_t)(b * 16 + hh) * 2048 + s) * 64 + kk;
                size_t i1 = i0 + 8 * 64;
                uint32_t hi, lo;
                split2(C[mf][nf][0] * sc, C[mf][nf][1] * sc, hi, lo);
                *(uint32_t*)&dh[i0] = hi;  *(uint32_t*)&dl[i0] = lo;
                split2(C[mf][nf][2] * sc, C[mf][nf][3] * sc, hi, lo);
                *(uint32_t*)&dh[i1] = hi;  *(uint32_t*)&dl[i1] = lo;
            }
        }
    }
}

// ---------------------------------------------------------------------------
// Flash attention (causal), 256 thr, q-tile 128, kv-tiles 64.
// Q staged through KV buffer 0 (then lives in regs) -> smem = 2 KV stages only
// => 72 KB => 2 CTAs/SM.
// ---------------------------------------------------------------------------
__global__ __launch_bounds__(256, 2) void attn_kernel()
{
    extern __shared__ __nv_bfloat16 dsm[];
    constexpr uint32_t KARR = 9216, KSTG = 36864;   // total dyn smem = 73728

    const int qb = (int)gridDim.x - 1 - (int)blockIdx.x;  // heavy blocks first
    const int q0 = qb * 128;
    const int bh = blockIdx.y;
    const int tid = threadIdx.x;
    const int w = tid >> 5, lane = tid & 31;
    const int gr = lane >> 2, tg = lane & 3;
    const size_t seqbase = (size_t)bh * 2048;
    const uint32_t sbase = smem_u32(dsm);

    // stage Q into buffer 0 (Qh at +0, Ql at +18432; row stride 144B)
    {
        const __nv_bfloat16* qh = g_qh + (seqbase + q0) * 64;
        const __nv_bfloat16* ql = g_ql + (seqbase + q0) * 64;
        #pragma unroll
        for (int i = 0; i < 4; i++) {
            int c = tid + 256 * i;
            int row = c >> 3, c8 = c & 7;
            uint32_t so = (uint32_t)(row * 144 + c8 * 16);
            size_t go = (size_t)row * 64 + c8 * 8;
            cp16(sbase + so,         qh + go);
            cp16(sbase + 18432 + so, ql + go);
        }
        CP_COMMIT();
    }

    auto stage_kv = [&](int it, int buf) {
        const int kv0 = it * 64;
        const uint32_t sa = sbase + (uint32_t)buf * KSTG;
        const __nv_bfloat16* kh = g_kh + (seqbase + kv0) * 64;
        const __nv_bfloat16* kl = g_kl + (seqbase + kv0) * 64;
        const __nv_bfloat16* vh = g_vh + (seqbase + kv0) * 64;
        const __nv_bfloat16* vl = g_vl + (seqbase + kv0) * 64;
        #pragma unroll
        for (int i = 0; i < 2; i++) {
            int c = tid + 256 * i;
            int row = c >> 3, c8 = c & 7;
            uint32_t so = (uint32_t)(row * 144 + c8 * 16);
            size_t go = (size_t)row * 64 + c8 * 8;
            cp16(sa + so,            kh + go);
            cp16(sa + KARR + so,     kl + go);
            cp16(sa + 2 * KARR + so, vh + go);
            cp16(sa + 3 * KARR + so, vl + go);
        }
        CP_COMMIT();
    };

    const int nt = qb * 2 + 2;
    stage_kv(0, 1);        // KV0 -> buffer 1 while Q occupies buffer 0
    CP_WAIT(1);            // Q group complete
    __syncthreads();

    // Q frags from buffer 0
    uint32_t Qh[4][4], Ql[4][4];
    {
        const uint32_t q_rowb = (uint32_t)(w * 16 + (lane & 7) + ((lane & 8) ? 8 : 0));
        const uint32_t q_coff = (lane & 16) ? 8 : 0;
        #pragma unroll
        for (int ks = 0; ks < 4; ks++) {
            uint32_t ad = sbase + q_rowb * 144 + (ks * 16 + q_coff) * 2;
            LDSM_X4(Qh[ks], ad);
            LDSM_X4(Ql[ks], ad + 18432);
        }
    }
    __syncthreads();       // all warps done reading Q from buffer 0

    float O[8][4];
    #pragma unroll
    for (int nf = 0; nf < 8; nf++)
        #pragma unroll
        for (int c = 0; c < 4; c++) O[nf][c] = 0.0f;
    float m0v = -1e30f, m1v = -1e30f, l0v = 0.0f, l1v = 0.0f;
    const int wrow = q0 + w * 16;

    const uint32_t k_rowb = (uint32_t)((lane & 7) + ((lane & 16) ? 8 : 0));
    const uint32_t k_coff = (lane & 8) ? 8 : 0;
    const uint32_t v_coff = (lane & 16) ? 8 : 0;

    for (int it = 0; it < nt; it++) {
        const int buf = 1 - (it & 1);  // KV_it parity (KV0 in buf1)
        if (it + 1 < nt) { stage_kv(it + 1, 1 - buf); CP_WAIT(1); }
        else             { CP_WAIT(0); }
        __syncthreads();
        const int kv0 = it * 64;

        if (kv0 <= wrow + 15) {
            const uint32_t sa = sbase + (uint32_t)buf * KSTG;

            // S = Q @ K^T
            float Sf[8][4];
            #pragma unroll
            for (int nf = 0; nf < 8; nf++)
                #pragma unroll
                for (int c = 0; c < 4; c++) Sf[nf][c] = 0.0f;

            #pragma unroll
            for (int ks = 0; ks < 4; ks++) {
                const uint32_t kcol = (uint32_t)(ks * 16) + k_coff;
                #pragma unroll
                for (int np = 0; np < 4; np++) {
                    uint32_t bd = sa + (k_rowb + np * 16) * 144 + kcol * 2;
                    uint32_t rh[4], rl[4];
                    LDSM_X4(rh, bd);
                    LDSM_X4(rl, bd + KARR);
                    mma_bf16(Sf[np * 2],     Qh[ks], rh[0], rh[1]);
                    mma_bf16(Sf[np * 2],     Qh[ks], rl[0], rl[1]);
                    mma_bf16(Sf[np * 2],     Ql[ks], rh[0], rh[1]);
                    mma_bf16(Sf[np * 2 + 1], Qh[ks], rh[2], rh[3]);
                    mma_bf16(Sf[np * 2 + 1], Qh[ks], rl[2], rl[3]);
                    mma_bf16(Sf[np * 2 + 1], Ql[ks], rh[2], rh[3]);
                }
            }

            // causal mask (boundary tiles only)
            if (kv0 + 63 > wrow) {
                const int r0g = wrow + gr;
                #pragma unroll
                for (int nf = 0; nf < 8; nf++) {
                    int col = kv0 + nf * 8 + tg * 2;
                    if (col     > r0g)     Sf[nf][0] = -1e30f;
                    if (col + 1 > r0g)     Sf[nf][1] = -1e30f;
                    if (col     > r0g + 8) Sf[nf][2] = -1e30f;
                    if (col + 1 > r0g + 8) Sf[nf][3] = -1e30f;
                }
            }

            // online softmax (base-2; q pre-scaled)
            float mx0 = -1e30f, mx1 = -1e30f;
            #pragma unroll
            for (int nf = 0; nf < 8; nf++) {
                mx0 = fmaxf(mx0, fmaxf(Sf[nf][0], Sf[nf][1]));
                mx1 = fmaxf(mx1, fmaxf(Sf[nf][2], Sf[nf][3]));
            }
            mx0 = fmaxf(mx0, __shfl_xor_sync(0xffffffffu, mx0, 1));
            mx0 = fmaxf(mx0, __shfl_xor_sync(0xffffffffu, mx0, 2));
            mx1 = fmaxf(mx1, __shfl_xor_sync(0xffffffffu, mx1, 1));
            mx1 = fmaxf(mx1, __shfl_xor_sync(0xffffffffu, mx1, 2));

            float mn0 = fmaxf(m0v, mx0), mn1 = fmaxf(m1v, mx1);
            float a0 = fast_exp2(m0v - mn0), a1 = fast_exp2(m1v - mn1);
            float s0 = 0.0f, s1 = 0.0f;
            #pragma unroll
            for (int nf = 0; nf < 8; nf++) {
                Sf[nf][0] = fast_exp2(Sf[nf][0] - mn0); s0 += Sf[nf][0];
                Sf[nf][1] = fast_exp2(Sf[nf][1] - mn0); s0 += Sf[nf][1];
                Sf[nf][2] = fast_exp2(Sf[nf][2] - mn1); s1 += Sf[nf][2];
                Sf[nf][3] = fast_exp2(Sf[nf][3] - mn1); s1 += Sf[nf][3];
            }
            s0 += __shfl_xor_sync(0xffffffffu, s0, 1);
            s0 += __shfl_xor_sync(0xffffffffu, s0, 2);
            s1 += __shfl_xor_sync(0xffffffffu, s1, 1);
            s1 += __shfl_xor_sync(0xffffffffu, s1, 2);

            l0v = l0v * a0 + s0;  l1v = l1v * a1 + s1;
            m0v = mn0;            m1v = mn1;
            #pragma unroll
            for (int nf = 0; nf < 8; nf++) {
                O[nf][0] *= a0; O[nf][1] *= a0;
                O[nf][2] *= a1; O[nf][3] *= a1;
            }

            // O += P @ V   (V row-major in smem; ldmatrix.trans)
            #pragma unroll
            for (int ks = 0; ks < 4; ks++) {
                uint32_t Ph[4], Pl[4];
                split2(Sf[2 * ks][0],     Sf[2 * ks][1],     Ph[0], Pl[0]);
                split2(Sf[2 * ks][2],     Sf[2 * ks][3],     Ph[1], Pl[1]);
                split2(Sf[2 * ks + 1][0], Sf[2 * ks + 1][1], Ph[2], Pl[2]);
                split2(Sf[2 * ks + 1][2], Sf[2 * ks + 1][3], Ph[3], Pl[3]);
                const uint32_t v_rowb = (uint32_t)(ks * 16 + (lane & 15));
                #pragma unroll
                for (int np = 0; np < 4; np++) {
                    uint32_t vd = sa + 2 * KARR + v_rowb * 144
                                + ((uint32_t)(np * 16) + v_coff) * 2;
                    uint32_t rh[4], rl[4];
                    LDSM_X4T(rh, vd);
                    LDSM_X4T(rl, vd + KARR);
                    mma_bf16(O[np * 2],     Ph, rh[0], rh[1]);
                    mma_bf16(O[np * 2],     Ph, rl[0], rl[1]);
                    mma_bf16(O[np * 2],     Pl, rh[0], rh[1]);
                    mma_bf16(O[np * 2 + 1], Ph, rh[2], rh[3]);
                    mma_bf16(O[np * 2 + 1], Ph, rl[2], rl[3]);
                    mma_bf16(O[np * 2 + 1], Pl, rh[2], rh[3]);
                }
            }
        }
        __syncthreads();
    }

    // epilogue: normalize, split, write concat-head layout
    const float inv0 = 1.0f / l0v, inv1 = 1.0f / l1v;
    const int b = bh >> 4, h = bh & 15;
    const int row0 = q0 + w * 16 + gr;
    const size_t base0 = ((size_t)(b * 2048) + row0) * 1024 + h * 64;
    const size_t base1 = base0 + (size_t)8 * 1024;
    #pragma unroll
    for (int nf = 0; nf < 8; nf++) {
        int c = nf * 8 + tg * 2;
        uint32_t hi, lo;
        split2(O[nf][0] * inv0, O[nf][1] * inv0, hi, lo);
        *(uint32_t*)&g_atth[base0 + c] = hi;
        *(uint32_t*)&g_attl[base0 + c] = lo;
        split2(O[nf][2] * inv1, O[nf][3] * inv1, hi, lo);
        *(uint32_t*)&g_atth[base1 + c] = hi;
        *(uint32_t*)&g_attl[base1 + c] = lo;
    }
}

// ---------------------------------------------------------------------------
extern "C" void kernel_launch(void* const* d_in, const int* in_sizes, int n_in,
                              void* d_out, int out_size)
{
    const float* x  = (const float*)d_in[0];
    const float* Wq = (const float*)d_in[1];
    const float* Wk = (const float*)d_in[2];
    const float* Wv = (const float*)d_in[3];
    const float* Wo = (const float*)d_in[4];
    float* out = (float*)d_out;

    void *p_xh, *p_xl, *p_wh, *p_wl, *p_woh, *p_wol, *p_atth, *p_attl;
    cudaGetSymbolAddress(&p_xh,  g_xh);   cudaGetSymbolAddress(&p_xl,  g_xl);
    cudaGetSymbolAddress(&p_wh,  g_wh);   cudaGetSymbolAddress(&p_wl,  g_wl);
    cudaGetSymbolAddress(&p_woh, g_woh);  cudaGetSymbolAddress(&p_wol, g_wol);
    cudaGetSymbolAddress(&p_atth, g_atth); cudaGetSymbolAddress(&p_attl, g_attl);

    const int gemm_shm = 81920;
    const int attn_shm = 73728;
    cudaFuncSetAttribute(gemm_kernel, cudaFuncAttributeMaxDynamicSharedMemorySize, gemm_shm);
    cudaFuncSetAttribute(attn_kernel, cudaFuncAttributeMaxDynamicSharedMemorySize, attn_shm);

    conv_split_kernel<<<8192, 256>>>((const float4*)x,
        (uint32_t*)p_xh, (uint32_t*)p_xl, 2097152);
    conv_split_kernel<<<1024, 256>>>((const float4*)Wo,
        (uint32_t*)p_woh, (uint32_t*)p_wol, 262144);

    wtrans_kernel<<<dim3(48, 16), 256>>>(Wq, Wk, Wv);

    gemm_kernel<<<dim3(24, 64), 256, gemm_shm>>>(
        (const __nv_bfloat16*)p_xh, (const __nv_bfloat16*)p_xl,
        (const __nv_bfloat16*)p_wh, (const __nv_bfloat16*)p_wl, nullptr, 0);

    attn_kernel<<<dim3(S_ / 128, 64), 256, attn_shm>>>();

    gemm_kernel<<<dim3(8, 64), 256, gemm_shm>>>(
        (const __nv_bfloat16*)p_atth, (const __nv_bfloat16*)p_attl,
        (const __nv_bfloat16*)p_woh, (const __nv_bfloat16*)p_wol, out, 1);
}